// round 14
// baseline (speedup 1.0000x reference)
#include <cuda_runtime.h>
#include <math.h>

// Problem shape (fixed by reference setup_inputs)
#define B     32
#define HW    12544
#define C     256
#define CR    16

#define GROUP 4               // batches per phase group (51.4 MB < L2)
#define NGRP  (B / GROUP)     // 8 groups -> 9 phases
#define SPL   196             // chunks per batch
#define CPOS  64              // positions per chunk (196*64 = 12544)
#define GB    (GROUP * SPL)   // 784 blocks per role -> 1568 per phase
#define PF    8               // prefetch depth for scale role

// Scratch (no cudaMalloc); zero-init at load, self-resetting each run
__device__ __align__(16) float        g_sums[B * C];
__device__ __align__(16) float        g_se[B * C];
__device__               unsigned int g_cnt[B];

// ---------------------------------------------------------------------------
// Phase kernel. Blocks [0,GB): pool group p (skip if p==NGRP).
//               Blocks [GB,2GB): scale group p-1 from L2 (skip if p==0).
// Stores: plain (st.global default). Scale reads: __ldcs (evict-first, dead
// after use -> keeps the freshly pooled next group resident in L2).
// ---------------------------------------------------------------------------
__global__ __launch_bounds__(256) void se_phase_kernel(
    int p,
    const float* __restrict__ in,
    const float* __restrict__ w1, const float* __restrict__ bb1,
    const float* __restrict__ w2, const float* __restrict__ bb2,
    float* __restrict__ out)
{
    const int tid  = threadIdx.x;
    const int qid  = tid & 63;
    const int prow = tid >> 6;

    const float4* in4  = reinterpret_cast<const float4*>(in);
    float4*       out4 = reinterpret_cast<float4*>(out);

    if (blockIdx.x < GB) {
        // ------------------------- POOL role -------------------------
        if (p == NGRP) return;
        const int b = GROUP * p + blockIdx.x / SPL;
        const int s = blockIdx.x % SPL;

        const size_t base = ((size_t)b * HW + s * CPOS + prow) * 64 + qid;

        // 16 loads, 4 independent accumulator chains
        float4 a0 = make_float4(0.f,0.f,0.f,0.f);
        float4 a1 = make_float4(0.f,0.f,0.f,0.f);
        float4 a2 = make_float4(0.f,0.f,0.f,0.f);
        float4 a3 = make_float4(0.f,0.f,0.f,0.f);
        #pragma unroll
        for (int k = 0; k < 16; k += 4) {
            float4 v0 = in4[base + (size_t)(k + 0) * 256];
            float4 v1 = in4[base + (size_t)(k + 1) * 256];
            float4 v2 = in4[base + (size_t)(k + 2) * 256];
            float4 v3 = in4[base + (size_t)(k + 3) * 256];
            a0.x += v0.x; a0.y += v0.y; a0.z += v0.z; a0.w += v0.w;
            a1.x += v1.x; a1.y += v1.y; a1.z += v1.z; a1.w += v1.w;
            a2.x += v2.x; a2.y += v2.y; a2.z += v2.z; a2.w += v2.w;
            a3.x += v3.x; a3.y += v3.y; a3.z += v3.z; a3.w += v3.w;
        }
        a0.x += a1.x + a2.x + a3.x;
        a0.y += a1.y + a2.y + a3.y;
        a0.z += a1.z + a2.z + a3.z;
        a0.w += a1.w + a2.w + a3.w;

        __shared__ __align__(16) float4 s_red[256];
        __shared__ int s_last;
        s_red[tid] = a0;
        __syncthreads();
        if (prow == 0) {
            float4 r0 = s_red[qid],       r1 = s_red[qid + 64];
            float4 r2 = s_red[qid + 128], r3 = s_red[qid + 192];
            float* dst = &g_sums[b * C + 4 * qid];
            atomicAdd(dst + 0, r0.x + r1.x + r2.x + r3.x);
            atomicAdd(dst + 1, r0.y + r1.y + r2.y + r3.y);
            atomicAdd(dst + 2, r0.z + r1.z + r2.z + r3.z);
            atomicAdd(dst + 3, r0.w + r1.w + r2.w + r3.w);
            __threadfence();
        }
        __syncthreads();
        if (tid == 0) {
            __threadfence();
            unsigned int old = atomicAdd(&g_cnt[b], 1u);
            s_last = (old == SPL - 1);
            if (s_last) g_cnt[b] = 0u;   // self-reset for next graph replay
        }
        __syncthreads();
        if (!s_last) return;
        __threadfence();   // acquire: all blocks' atomics visible

        // ---- last block of batch b: tiny MLP -> g_se[b], reset sums ----
        __shared__ __align__(16) float s_mean[C];
        __shared__ float s_part[4][CR];
        __shared__ float s_h[CR];

        s_mean[tid] = g_sums[b * C + tid] * (1.0f / (float)HW);
        g_sums[b * C + tid] = 0.0f;      // reset for next replay
        __syncthreads();
        if (tid < 64) {
            int j = tid & 15, part = tid >> 4, c0 = part * 64;
            float acc = 0.0f;
            #pragma unroll 8
            for (int c = c0; c < c0 + 64; c++)
                acc += s_mean[c] * w1[c * CR + j];
            s_part[part][j] = acc;
        }
        __syncthreads();
        if (tid < CR) {
            float acc = bb1[tid] + s_part[0][tid] + s_part[1][tid]
                                 + s_part[2][tid] + s_part[3][tid];
            s_h[tid] = fmaxf(acc, 0.0f);
        }
        __syncthreads();
        {
            float acc = bb2[tid];
            #pragma unroll
            for (int j = 0; j < CR; j++)
                acc += s_h[j] * w2[j * C + tid];
            g_se[b * C + tid] = 1.0f / (1.0f + __expf(-acc));
        }
    } else {
        // ------------------------- SCALE role -------------------------
        if (p == 0) return;
        const int blk = blockIdx.x - GB;
        const int b = GROUP * (p - 1) + blk / SPL;
        const int s = blk % SPL;

        const size_t base = ((size_t)b * HW + s * CPOS + prow) * 64 + qid;

        // prefetch first half (loads fly while we fetch g_se)
        float4 pf[PF];
        #pragma unroll
        for (int k = 0; k < PF; k++)
            pf[k] = __ldcs(&in4[base + (size_t)k * 256]);

        __shared__ __align__(16) float s_se[C];
        s_se[tid] = g_se[b * C + tid];   // written last phase (kernel boundary)
        __syncthreads();
        const float4 sv = *reinterpret_cast<const float4*>(&s_se[4 * qid]);

        #pragma unroll
        for (int k = 0; k < PF; k++) {
            float4 v = pf[k];
            v.x *= sv.x; v.y *= sv.y; v.z *= sv.z; v.w *= sv.w;
            out4[base + (size_t)k * 256] = v;
        }
        #pragma unroll
        for (int k = PF; k < 16; k++) {
            float4 v = __ldcs(&in4[base + (size_t)k * 256]);  // L2 hit, dead after
            v.x *= sv.x; v.y *= sv.y; v.z *= sv.z; v.w *= sv.w;
            out4[base + (size_t)k * 256] = v;
        }
    }
}

// ---------------------------------------------------------------------------
extern "C" void kernel_launch(void* const* d_in, const int* in_sizes, int n_in,
                              void* d_out, int out_size)
{
    const float* in = (const float*)d_in[0];
    const float* w1 = (const float*)d_in[1];
    const float* b1 = (const float*)d_in[2];
    const float* w2 = (const float*)d_in[3];
    const float* b2 = (const float*)d_in[4];
    float* out = (float*)d_out;

    for (int p = 0; p <= NGRP; p++)
        se_phase_kernel<<<2 * GB, 256>>>(p, in, w1, b1, w2, b2, out);
}

// round 15
// speedup vs baseline: 1.4151x; 1.4151x over previous
#include <cuda_runtime.h>
#include <math.h>

// Problem shape (fixed by reference setup_inputs)
#define B  32
#define HH 112
#define WW 112
#define HW (HH*WW)        // 12544
#define C  256
#define CR 16             // C / r

#define SPLITS 49
#define CHUNK  (HW / SPLITS)   // 256 positions per block
#define PF     8               // prefetched float4 per thread (covers PDL wait)

// Scratch (no cudaMalloc allowed)
__device__ __align__(16) float g_part[B * SPLITS * C];  // per-block partials
__device__ __align__(16) float g_se[B * C];             // sigmoid gates
__device__ unsigned int g_cnt[B];                       // self-resetting counters

// ---------------------------------------------------------------------------
// Kernel 1: partial spatial sums + (last block per batch) reduce + MLP.
// Fires the PDL trigger right after publishing partials, so the scale kernel
// ramps up while the tail wave + MLP epilogue finish.
// ---------------------------------------------------------------------------
__global__ __launch_bounds__(256) void se_pool_mlp_kernel(
    const float* __restrict__ in,
    const float* __restrict__ w1, const float* __restrict__ bb1,
    const float* __restrict__ w2, const float* __restrict__ bb2)
{
    int blk = blockIdx.x;
    int b = blk / SPLITS;
    int s = blk % SPLITS;
    int tid = threadIdx.x;
    int qid  = tid & 63;
    int prow = tid >> 6;   // 0..3

    const float4* __restrict__ in4 =
        reinterpret_cast<const float4*>(in + (size_t)b * HW * C);

    size_t base = ((size_t)s * CHUNK + prow) * 64 + qid;  // float4 index

    float4 a0 = make_float4(0.f, 0.f, 0.f, 0.f);
    float4 a1 = make_float4(0.f, 0.f, 0.f, 0.f);

    #pragma unroll 8
    for (int k = 0; k < 64; k += 2) {
        float4 v0 = in4[base + (size_t)(4 * k)     * 64];
        float4 v1 = in4[base + (size_t)(4 * k + 4) * 64];
        a0.x += v0.x; a0.y += v0.y; a0.z += v0.z; a0.w += v0.w;
        a1.x += v1.x; a1.y += v1.y; a1.z += v1.z; a1.w += v1.w;
    }
    a0.x += a1.x; a0.y += a1.y; a0.z += a1.z; a0.w += a1.w;

    __shared__ __align__(16) float4 s_red[256];
    s_red[tid] = a0;
    __syncthreads();
    if (prow == 0) {
        float4 r0 = s_red[qid];
        float4 r1 = s_red[qid + 64];
        float4 r2 = s_red[qid + 128];
        float4 r3 = s_red[qid + 192];
        float4 r;
        r.x = r0.x + r1.x + r2.x + r3.x;
        r.y = r0.y + r1.y + r2.y + r3.y;
        r.z = r0.z + r1.z + r2.z + r3.z;
        r.w = r0.w + r1.w + r2.w + r3.w;
        reinterpret_cast<float4*>(&g_part[(size_t)blk * C])[qid] = r;
    }

    // PDL: allow the dependent (scale) kernel to start launching now.
    asm volatile("griddepcontrol.launch_dependents;");

    // ---- last-arriving block of this batch runs the MLP ----
    __threadfence();
    __shared__ bool s_last;
    __syncthreads();
    if (tid == 0) {
        unsigned int old = atomicAdd(&g_cnt[b], 1u);
        s_last = (old == SPLITS - 1);
        if (s_last) g_cnt[b] = 0;   // self-reset for next replay
    }
    __syncthreads();
    if (!s_last) return;
    __threadfence();   // acquire: make all blocks' partials visible

    __shared__ __align__(16) float s_mean[C];
    __shared__ float s_part[4][CR];
    __shared__ float s_h[CR];

    {
        float sum = 0.0f;
        const float* p = &g_part[(size_t)b * SPLITS * C + tid];
        #pragma unroll 7
        for (int k = 0; k < SPLITS; k++)
            sum += p[(size_t)k * C];
        s_mean[tid] = sum * (1.0f / (float)HW);
    }
    __syncthreads();

    if (tid < 64) {
        int j    = tid & 15;
        int part = tid >> 4;
        float acc = 0.0f;
        int c0 = part * 64;
        #pragma unroll 8
        for (int c = c0; c < c0 + 64; c++)
            acc += s_mean[c] * w1[c * CR + j];
        s_part[part][j] = acc;
    }
    __syncthreads();
    if (tid < CR) {
        float acc = bb1[tid] + s_part[0][tid] + s_part[1][tid]
                             + s_part[2][tid] + s_part[3][tid];
        s_h[tid] = fmaxf(acc, 0.0f);   // relu
    }
    __syncthreads();

    {
        float acc = bb2[tid];
        #pragma unroll
        for (int j = 0; j < CR; j++)
            acc += s_h[j] * w2[j * C + tid];
        g_se[b * C + tid] = 1.0f / (1.0f + __expf(-acc));  // sigmoid
    }
}

// ---------------------------------------------------------------------------
// Kernel 2: broadcast multiply. Launched with PDL — starts during pool tail.
// Prefetch input (read-only, safe pre-wait), then griddepcontrol.wait before
// reading g_se. Reversed block order: first blocks read the addresses the
// pool touched last (L2 reuse + overlap with pool tail).
// ---------------------------------------------------------------------------
__global__ __launch_bounds__(256) void se_scale_kernel(
    const float* __restrict__ in, float* __restrict__ out)
{
    int rblk = (B * SPLITS - 1) - blockIdx.x;   // reversed mapping
    int b = rblk / SPLITS;
    int s = rblk % SPLITS;
    int tid = threadIdx.x;
    int qid  = tid & 63;
    int prow = tid >> 6;

    const float4* __restrict__ in4 =
        reinterpret_cast<const float4*>(in + (size_t)b * HW * C);
    float4* __restrict__ out4 =
        reinterpret_cast<float4*>(out) + (size_t)b * HW * 64;

    size_t base = ((size_t)s * CHUNK + prow) * 64 + qid;

    // issue prefetch loads FIRST (input is never written — safe before wait)
    float4 pf[PF];
    #pragma unroll
    for (int k = 0; k < PF; k++)
        pf[k] = in4[base + (size_t)(4 * k) * 64];

    // wait for the pool kernel's full completion (g_se visible)
    asm volatile("griddepcontrol.wait;" ::: "memory");

    __shared__ __align__(16) float s_se[C];
    s_se[tid] = g_se[b * C + tid];
    __syncthreads();
    float4 sv = *reinterpret_cast<const float4*>(&s_se[4 * qid]);

    // drain prefetched data
    #pragma unroll
    for (int k = 0; k < PF; k++) {
        float4 v = pf[k];
        v.x *= sv.x; v.y *= sv.y; v.z *= sv.z; v.w *= sv.w;
        out4[base + (size_t)(4 * k) * 64] = v;
    }

    // stream the remaining positions
    #pragma unroll 8
    for (int k = PF; k < 64; k++) {
        size_t idx = base + (size_t)(4 * k) * 64;
        float4 v = in4[idx];
        v.x *= sv.x; v.y *= sv.y; v.z *= sv.z; v.w *= sv.w;
        out4[idx] = v;
    }
}

// ---------------------------------------------------------------------------
extern "C" void kernel_launch(void* const* d_in, const int* in_sizes, int n_in,
                              void* d_out, int out_size)
{
    const float* in = (const float*)d_in[0];
    const float* w1 = (const float*)d_in[1];
    const float* b1 = (const float*)d_in[2];
    const float* w2 = (const float*)d_in[3];
    const float* b2 = (const float*)d_in[4];
    float* out = (float*)d_out;

    se_pool_mlp_kernel<<<B * SPLITS, 256>>>(in, w1, b1, w2, b2);

    // PDL launch for the scale kernel
    cudaLaunchConfig_t cfg = {};
    cfg.gridDim  = dim3(B * SPLITS);
    cfg.blockDim = dim3(256);
    cfg.stream   = 0;
    cudaLaunchAttribute attrs[1];
    attrs[0].id = cudaLaunchAttributeProgrammaticStreamSerialization;
    attrs[0].val.programmaticStreamSerializationAllowed = 1;
    cfg.attrs    = attrs;
    cfg.numAttrs = 1;
    cudaLaunchKernelEx(&cfg, se_scale_kernel, in, out);
}

// round 16
// speedup vs baseline: 1.4201x; 1.0035x over previous
#include <cuda_runtime.h>
#include <math.h>

// Problem shape (fixed by reference setup_inputs)
#define B  32
#define HH 112
#define WW 112
#define HW (HH*WW)        // 12544
#define C  256
#define CR 16             // C / r

#define SPLITS 49
#define CHUNK  (HW / SPLITS)   // 256 positions per block
#define PF     8               // prefetched float4 per thread (covers PDL wait)

// Scratch (no cudaMalloc allowed)
__device__ __align__(16) float g_part[B * SPLITS * C];  // per-block partials
__device__ __align__(16) float g_se[B * C];             // sigmoid gates
__device__ unsigned int g_cnt[B];                       // self-resetting counters

// ---------------------------------------------------------------------------
// Kernel 1: partial spatial sums + (last block per batch) reduce + MLP.
// Fires the PDL trigger right after publishing partials, so the scale kernel
// ramps up while the tail wave + MLP epilogue finish.
// ---------------------------------------------------------------------------
__global__ __launch_bounds__(256) void se_pool_mlp_kernel(
    const float* __restrict__ in,
    const float* __restrict__ w1, const float* __restrict__ bb1,
    const float* __restrict__ w2, const float* __restrict__ bb2)
{
    int blk = blockIdx.x;
    int b = blk / SPLITS;
    int s = blk % SPLITS;
    int tid = threadIdx.x;
    int qid  = tid & 63;
    int prow = tid >> 6;   // 0..3

    const float4* __restrict__ in4 =
        reinterpret_cast<const float4*>(in + (size_t)b * HW * C);

    size_t base = ((size_t)s * CHUNK + prow) * 64 + qid;  // float4 index

    float4 a0 = make_float4(0.f, 0.f, 0.f, 0.f);
    float4 a1 = make_float4(0.f, 0.f, 0.f, 0.f);

    #pragma unroll 8
    for (int k = 0; k < 64; k += 2) {
        float4 v0 = in4[base + (size_t)(4 * k)     * 64];
        float4 v1 = in4[base + (size_t)(4 * k + 4) * 64];
        a0.x += v0.x; a0.y += v0.y; a0.z += v0.z; a0.w += v0.w;
        a1.x += v1.x; a1.y += v1.y; a1.z += v1.z; a1.w += v1.w;
    }
    a0.x += a1.x; a0.y += a1.y; a0.z += a1.z; a0.w += a1.w;

    __shared__ __align__(16) float4 s_red[256];
    s_red[tid] = a0;
    __syncthreads();
    if (prow == 0) {
        float4 r0 = s_red[qid];
        float4 r1 = s_red[qid + 64];
        float4 r2 = s_red[qid + 128];
        float4 r3 = s_red[qid + 192];
        float4 r;
        r.x = r0.x + r1.x + r2.x + r3.x;
        r.y = r0.y + r1.y + r2.y + r3.y;
        r.z = r0.z + r1.z + r2.z + r3.z;
        r.w = r0.w + r1.w + r2.w + r3.w;
        reinterpret_cast<float4*>(&g_part[(size_t)blk * C])[qid] = r;
    }

    // PDL: allow the dependent (scale) kernel to start launching now.
    asm volatile("griddepcontrol.launch_dependents;");

    // ---- last-arriving block of this batch runs the MLP ----
    __threadfence();
    __shared__ bool s_last;
    __syncthreads();
    if (tid == 0) {
        unsigned int old = atomicAdd(&g_cnt[b], 1u);
        s_last = (old == SPLITS - 1);
        if (s_last) g_cnt[b] = 0;   // self-reset for next replay
    }
    __syncthreads();
    if (!s_last) return;
    __threadfence();   // acquire: make all blocks' partials visible

    __shared__ __align__(16) float s_mean[C];
    __shared__ float s_part[4][CR];
    __shared__ float s_h[CR];

    {
        float sum = 0.0f;
        const float* p = &g_part[(size_t)b * SPLITS * C + tid];
        #pragma unroll 7
        for (int k = 0; k < SPLITS; k++)
            sum += p[(size_t)k * C];
        s_mean[tid] = sum * (1.0f / (float)HW);
    }
    __syncthreads();

    if (tid < 64) {
        int j    = tid & 15;
        int part = tid >> 4;
        float acc = 0.0f;
        int c0 = part * 64;
        #pragma unroll 8
        for (int c = c0; c < c0 + 64; c++)
            acc += s_mean[c] * w1[c * CR + j];
        s_part[part][j] = acc;
    }
    __syncthreads();
    if (tid < CR) {
        float acc = bb1[tid] + s_part[0][tid] + s_part[1][tid]
                             + s_part[2][tid] + s_part[3][tid];
        s_h[tid] = fmaxf(acc, 0.0f);   // relu
    }
    __syncthreads();

    {
        float acc = bb2[tid];
        #pragma unroll
        for (int j = 0; j < CR; j++)
            acc += s_h[j] * w2[j * C + tid];
        g_se[b * C + tid] = 1.0f / (1.0f + __expf(-acc));  // sigmoid
    }
}

// ---------------------------------------------------------------------------
// Kernel 2: broadcast multiply. Launched with PDL — starts during pool tail.
// Prefetch input (read-only, safe pre-wait), then griddepcontrol.wait before
// reading g_se. Reversed block order: first blocks read the addresses the
// pool touched last (L2 reuse + overlap with pool tail).
// ---------------------------------------------------------------------------
__global__ __launch_bounds__(256) void se_scale_kernel(
    const float* __restrict__ in, float* __restrict__ out)
{
    int rblk = (B * SPLITS - 1) - blockIdx.x;   // reversed mapping
    int b = rblk / SPLITS;
    int s = rblk % SPLITS;
    int tid = threadIdx.x;
    int qid  = tid & 63;
    int prow = tid >> 6;

    const float4* __restrict__ in4 =
        reinterpret_cast<const float4*>(in + (size_t)b * HW * C);
    float4* __restrict__ out4 =
        reinterpret_cast<float4*>(out) + (size_t)b * HW * 64;

    size_t base = ((size_t)s * CHUNK + prow) * 64 + qid;

    // issue prefetch loads FIRST (input is never written — safe before wait)
    float4 pf[PF];
    #pragma unroll
    for (int k = 0; k < PF; k++)
        pf[k] = in4[base + (size_t)(4 * k) * 64];

    // wait for the pool kernel's full completion (g_se visible)
    asm volatile("griddepcontrol.wait;" ::: "memory");

    __shared__ __align__(16) float s_se[C];
    s_se[tid] = g_se[b * C + tid];
    __syncthreads();
    float4 sv = *reinterpret_cast<const float4*>(&s_se[4 * qid]);

    // drain prefetched data
    #pragma unroll
    for (int k = 0; k < PF; k++) {
        float4 v = pf[k];
        v.x *= sv.x; v.y *= sv.y; v.z *= sv.z; v.w *= sv.w;
        out4[base + (size_t)(4 * k) * 64] = v;
    }

    // stream the remaining positions
    #pragma unroll 8
    for (int k = PF; k < 64; k++) {
        size_t idx = base + (size_t)(4 * k) * 64;
        float4 v = in4[idx];
        v.x *= sv.x; v.y *= sv.y; v.z *= sv.z; v.w *= sv.w;
        out4[idx] = v;
    }
}

// ---------------------------------------------------------------------------
extern "C" void kernel_launch(void* const* d_in, const int* in_sizes, int n_in,
                              void* d_out, int out_size)
{
    const float* in = (const float*)d_in[0];
    const float* w1 = (const float*)d_in[1];
    const float* b1 = (const float*)d_in[2];
    const float* w2 = (const float*)d_in[3];
    const float* b2 = (const float*)d_in[4];
    float* out = (float*)d_out;

    se_pool_mlp_kernel<<<B * SPLITS, 256>>>(in, w1, b1, w2, b2);

    // PDL launch for the scale kernel
    cudaLaunchConfig_t cfg = {};
    cfg.gridDim  = dim3(B * SPLITS);
    cfg.blockDim = dim3(256);
    cfg.stream   = 0;
    cudaLaunchAttribute attrs[1];
    attrs[0].id = cudaLaunchAttributeProgrammaticStreamSerialization;
    attrs[0].val.programmaticStreamSerializationAllowed = 1;
    cfg.attrs    = attrs;
    cfg.numAttrs = 1;
    cudaLaunchKernelEx(&cfg, se_scale_kernel, in, out);
}